// round 1
// baseline (speedup 1.0000x reference)
#include <cuda_runtime.h>
#include <cuda_bf16.h>
#include <cstdint>

// Problem constants
#define BB 4
#define TT 4096
#define DD 512

// Scratch (allocation-free rule: __device__ globals)
__device__ float    g_xn[(size_t)BB * TT * DD];   // normalized x, fp32
__device__ unsigned g_m[(size_t)BB * TT];         // per-row max sim, order-encoded float

// ---- order-preserving float <-> uint for atomicMax ----
__device__ __forceinline__ unsigned ford(float f) {
    unsigned u = __float_as_uint(f);
    return (u & 0x80000000u) ? ~u : (u | 0x80000000u);
}
__device__ __forceinline__ float funord(unsigned u) {
    return __uint_as_float((u & 0x80000000u) ? (u ^ 0x80000000u) : ~u);
}

// ============================================================
// Kernel A: per-row L2 normalize; seed g_m with ord(-2.0f)
// grid = B*T blocks, 128 threads; each thread handles one float4
// ============================================================
__global__ void normalize_kernel(const float* __restrict__ x) {
    int row = blockIdx.x;                  // 0 .. B*T-1
    int tid = threadIdx.x;                 // 0..127
    const float4* xin = reinterpret_cast<const float4*>(x + (size_t)row * DD);
    float4 v = xin[tid];
    float ss = v.x * v.x + v.y * v.y + v.z * v.z + v.w * v.w;

    // warp reduce
    #pragma unroll
    for (int off = 16; off > 0; off >>= 1)
        ss += __shfl_xor_sync(0xffffffffu, ss, off);

    __shared__ float warp_sums[4];
    int wid = tid >> 5, lid = tid & 31;
    if (lid == 0) warp_sums[wid] = ss;
    __syncthreads();
    float total = warp_sums[0] + warp_sums[1] + warp_sums[2] + warp_sums[3];
    float norm = sqrtf(total);
    float scale = 1.0f / fmaxf(norm, 1e-12f);

    v.x *= scale; v.y *= scale; v.z *= scale; v.w *= scale;
    float4* xo = reinterpret_cast<float4*>(g_xn + (size_t)row * DD);
    xo[tid] = v;

    if (tid == 0) g_m[row] = ford(-2.0f);
}

// ============================================================
// Kernel B: tiled sim-max.  D = x̂ x̂^T restricted to s<t, row max.
// Block tile 64(t) x 64(s), BK=32, 256 threads, 4x4 per thread.
// grid = (t_tiles=64, B=4, s_tiles=64); s_tile > t_tile => skip.
// ============================================================
#define BT 64
#define BS 64
#define BK 32
#define SPITCH 65   // padded row pitch (floats) for conflict-free column stores

__global__ __launch_bounds__(256, 2) void simmax_kernel() {
    const int t_tile = blockIdx.x;
    const int b      = blockIdx.y;
    const int s_tile = blockIdx.z;
    if (s_tile > t_tile) return;

    const int t0 = t_tile * BT;
    const int s0 = s_tile * BS;
    const bool diag = (s_tile == t_tile);

    __shared__ float As[BK * SPITCH];  // As[k][t_row]
    __shared__ float Bs[BK * SPITCH];  // Bs[k][s_row]

    const int tid = threadIdx.x;       // 0..255
    const int tx = tid & 15;           // s micro index
    const int ty = tid >> 4;           // t micro index

    const float* xa = g_xn + ((size_t)b * TT + t0) * DD;  // 64 t-rows
    const float* xb = g_xn + ((size_t)b * TT + s0) * DD;  // 64 s-rows

    float acc[4][4];
    #pragma unroll
    for (int i = 0; i < 4; i++)
        #pragma unroll
        for (int j = 0; j < 4; j++) acc[i][j] = 0.0f;

    for (int k0 = 0; k0 < DD; k0 += BK) {
        // Load 64 rows x 32 k as float4 quads: 512 quads, 2 per thread.
        #pragma unroll
        for (int q = 0; q < 2; q++) {
            int lidx = tid + q * 256;
            int row = lidx >> 3;        // 0..63
            int kq  = lidx & 7;         // 0..7 (float4 index)
            float4 va = *reinterpret_cast<const float4*>(xa + (size_t)row * DD + k0 + kq * 4);
            float4 vb = *reinterpret_cast<const float4*>(xb + (size_t)row * DD + k0 + kq * 4);
            int kbase = kq * 4;
            As[(kbase + 0) * SPITCH + row] = va.x;
            As[(kbase + 1) * SPITCH + row] = va.y;
            As[(kbase + 2) * SPITCH + row] = va.z;
            As[(kbase + 3) * SPITCH + row] = va.w;
            Bs[(kbase + 0) * SPITCH + row] = vb.x;
            Bs[(kbase + 1) * SPITCH + row] = vb.y;
            Bs[(kbase + 2) * SPITCH + row] = vb.z;
            Bs[(kbase + 3) * SPITCH + row] = vb.w;
        }
        __syncthreads();

        #pragma unroll
        for (int k = 0; k < BK; k++) {
            float a0 = As[k * SPITCH + ty * 4 + 0];
            float a1 = As[k * SPITCH + ty * 4 + 1];
            float a2 = As[k * SPITCH + ty * 4 + 2];
            float a3 = As[k * SPITCH + ty * 4 + 3];
            float b0 = Bs[k * SPITCH + tx * 4 + 0];
            float b1 = Bs[k * SPITCH + tx * 4 + 1];
            float b2 = Bs[k * SPITCH + tx * 4 + 2];
            float b3 = Bs[k * SPITCH + tx * 4 + 3];
            acc[0][0] += a0 * b0; acc[0][1] += a0 * b1; acc[0][2] += a0 * b2; acc[0][3] += a0 * b3;
            acc[1][0] += a1 * b0; acc[1][1] += a1 * b1; acc[1][2] += a1 * b2; acc[1][3] += a1 * b3;
            acc[2][0] += a2 * b0; acc[2][1] += a2 * b1; acc[2][2] += a2 * b2; acc[2][3] += a2 * b3;
            acc[3][0] += a3 * b0; acc[3][1] += a3 * b1; acc[3][2] += a3 * b2; acc[3][3] += a3 * b3;
        }
        __syncthreads();
    }

    // Row-max with causal mask (only s < t valid).
    #pragma unroll
    for (int i = 0; i < 4; i++) {
        int t_idx = ty * 4 + i;
        float rmax = -3.0f;
        #pragma unroll
        for (int j = 0; j < 4; j++) {
            int s_idx = tx * 4 + j;
            bool valid = diag ? ((s0 + s_idx) < (t0 + t_idx)) : true;
            if (valid) rmax = fmaxf(rmax, acc[i][j]);
        }
        // reduce across the 16 tx lanes (lanes grouped: lane = (ty&1)*16 + tx)
        #pragma unroll
        for (int off = 8; off > 0; off >>= 1)
            rmax = fmaxf(rmax, __shfl_xor_sync(0xffffffffu, rmax, off));
        if (tx == 0 && rmax > -2.5f)
            atomicMax(&g_m[(size_t)b * TT + t0 + t_idx], ford(rmax));
    }
}

// ============================================================
// Kernel C: gate + tanh-GELU epilogue, float4 vectorized.
// ============================================================
__global__ void gate_gelu_kernel(const float* __restrict__ x,
                                 const float* __restrict__ log_alpha,
                                 float* __restrict__ out) {
    size_t idx = (size_t)blockIdx.x * blockDim.x + threadIdx.x;   // float4 index
    size_t total4 = (size_t)BB * TT * DD / 4;
    if (idx >= total4) return;

    float la = *log_alpha;
    // softplus
    float alpha = (la > 20.0f) ? la : log1pf(expf(la));

    size_t row = idx / (DD / 4);
    float m = funord(g_m[row]);
    m = fmaxf(m, -1.0f);
    float gate = 1.0f + alpha * 0.5f * (1.0f - m);

    float4 v = reinterpret_cast<const float4*>(x)[idx];
    const float c = 0.7978845608028654f;
    float r[4] = {v.x, v.y, v.z, v.w};
    #pragma unroll
    for (int i = 0; i < 4; i++) {
        float xv = r[i] * gate;
        float t = tanhf(c * (xv + 0.044715f * xv * xv * xv));
        r[i] = 0.5f * xv * (1.0f + t);
    }
    float4 o = {r[0], r[1], r[2], r[3]};
    reinterpret_cast<float4*>(out)[idx] = o;
}

extern "C" void kernel_launch(void* const* d_in, const int* in_sizes, int n_in,
                              void* d_out, int out_size) {
    const float* x  = (const float*)d_in[0];
    const float* la = (const float*)d_in[1];
    float* out = (float*)d_out;

    normalize_kernel<<<BB * TT, 128>>>(x);

    dim3 grid(TT / BT, BB, TT / BS);
    simmax_kernel<<<grid, 256>>>();

    size_t total4 = (size_t)BB * TT * DD / 4;
    int threads = 256;
    int blocks = (int)((total4 + threads - 1) / threads);
    gate_gelu_kernel<<<blocks, threads>>>(x, la, out);
}

// round 3
// speedup vs baseline: 10.3870x; 10.3870x over previous
#include <cuda_runtime.h>
#include <cuda_bf16.h>
#include <cstdint>

// Problem constants
#define BB 4
#define TT 4096
#define DD 512

// ---------------- scratch (__device__ globals; no allocs allowed) ----------
__device__ __nv_bfloat16 g_xnb[(size_t)BB * TT * DD];  // normalized x, bf16
__device__ unsigned      g_m[(size_t)BB * TT];         // per-row max sim (order-encoded)

// ---- order-preserving float <-> uint for atomicMax ----
__device__ __forceinline__ unsigned ford(float f) {
    unsigned u = __float_as_uint(f);
    return (u & 0x80000000u) ? ~u : (u | 0x80000000u);
}
__device__ __forceinline__ float funord(unsigned u) {
    return __uint_as_float((u & 0x80000000u) ? (u ^ 0x80000000u) : ~u);
}

__device__ __forceinline__ uint32_t smem_u32(const void* p) {
    uint32_t a;
    asm("{ .reg .u64 t; cvta.to.shared.u64 t, %1; cvt.u32.u64 %0, t; }" : "=r"(a) : "l"(p));
    return a;
}

#define SWZ128(off) ((off) ^ (((off) >> 3) & 0x70))

#define CP_ASYNC16(sm, gm) \
    asm volatile("cp.async.cg.shared.global [%0], [%1], 16;" :: "r"(sm), "l"(gm) : "memory")
#define CP_COMMIT() asm volatile("cp.async.commit_group;" ::: "memory")
#define CP_WAIT1()  asm volatile("cp.async.wait_group 1;" ::: "memory")
#define CP_WAIT0()  asm volatile("cp.async.wait_group 0;" ::: "memory")

#define LDMATRIX_X4(r0, r1, r2, r3, addr) \
    asm volatile("ldmatrix.sync.aligned.m8n8.x4.shared.b16 {%0,%1,%2,%3}, [%4];" \
                 : "=r"(r0), "=r"(r1), "=r"(r2), "=r"(r3) : "r"(addr))

#define MMA_BF16(c0, c1, c2, c3, a0, a1, a2, a3, b0, b1) \
    asm volatile("mma.sync.aligned.m16n8k16.row.col.f32.bf16.bf16.f32 " \
                 "{%0,%1,%2,%3}, {%4,%5,%6,%7}, {%8,%9}, {%0,%1,%2,%3};" \
                 : "+f"(c0), "+f"(c1), "+f"(c2), "+f"(c3) \
                 : "r"(a0), "r"(a1), "r"(a2), "r"(a3), "r"(b0), "r"(b1))

// ============================================================
// Kernel A: per-row L2 normalize -> bf16; seed g_m with ord(-2)
// ============================================================
__global__ void normalize_kernel(const float* __restrict__ x) {
    int row = blockIdx.x;
    int tid = threadIdx.x;   // 0..127, 4 floats each
    const float4* xin = reinterpret_cast<const float4*>(x + (size_t)row * DD);
    float4 v = xin[tid];
    float ss = v.x * v.x + v.y * v.y + v.z * v.z + v.w * v.w;
    #pragma unroll
    for (int off = 16; off > 0; off >>= 1)
        ss += __shfl_xor_sync(0xffffffffu, ss, off);
    __shared__ float warp_sums[4];
    int wid = tid >> 5, lid = tid & 31;
    if (lid == 0) warp_sums[wid] = ss;
    __syncthreads();
    float total = warp_sums[0] + warp_sums[1] + warp_sums[2] + warp_sums[3];
    float scale = 1.0f / fmaxf(sqrtf(total), 1e-12f);

    __nv_bfloat162 p0 = __floats2bfloat162_rn(v.x * scale, v.y * scale);
    __nv_bfloat162 p1 = __floats2bfloat162_rn(v.z * scale, v.w * scale);
    uint2 o;
    o.x = *reinterpret_cast<unsigned*>(&p0);
    o.y = *reinterpret_cast<unsigned*>(&p1);
    reinterpret_cast<uint2*>(g_xnb + (size_t)row * DD)[tid] = o;

    if (tid == 0) g_m[row] = ford(-2.0f);
}

// ============================================================
// Kernel B: mma.sync bf16 sim-max. CTA tile 128x128, 8 warps
// (4m x 2n), warp tile 32x64, K in 8 chunks of 64, cp.async
// double buffer, SW128-swizzled smem, row-max from registers.
// grid = (528 lower-tri tile pairs, B)
// ============================================================
#define TM 128
#define KC 64
#define NCHUNK (DD / KC)     // 8
#define ROWB 128             // bytes per smem row (64 bf16)
#define BUF_BYTES (TM * ROWB)   // 16 KB per tile buffer
// smem: A0 | B0 | A1 | B1
#define SM_TOTAL (4 * BUF_BYTES)

__global__ __launch_bounds__(256) void simmax_mma_kernel() {
    extern __shared__ char smem[];
    const uint32_t smb = smem_u32(smem);
    const int tid = threadIdx.x;
    const int wid = tid >> 5;
    const int lane = tid & 31;

    // decode lower-triangular pair index -> (t_tile, s_tile)
    int p = blockIdx.x;
    int t_tile = (int)((sqrtf(8.0f * (float)p + 1.0f) - 1.0f) * 0.5f);
    while ((t_tile + 1) * (t_tile + 2) / 2 <= p) ++t_tile;
    while (t_tile * (t_tile + 1) / 2 > p) --t_tile;
    int s_tile = p - t_tile * (t_tile + 1) / 2;
    const int b = blockIdx.y;
    const int t0 = t_tile * TM;
    const int s0 = s_tile * TM;
    const bool diag = (s_tile == t_tile);

    const char* xa = reinterpret_cast<const char*>(g_xnb + ((size_t)b * TT + t0) * DD);
    const char* xb = reinterpret_cast<const char*>(g_xnb + ((size_t)b * TT + s0) * DD);

    const int warp_m = wid & 3;        // 0..3 -> 32 rows each
    const int warp_n = wid >> 2;       // 0..1 -> 64 cols each
    const int m0 = warp_m * 32;
    const int n0 = warp_n * 64;

    float acc[2][8][4];
    #pragma unroll
    for (int mi = 0; mi < 2; mi++)
        #pragma unroll
        for (int nj = 0; nj < 8; nj++)
            #pragma unroll
            for (int r = 0; r < 4; r++) acc[mi][nj][r] = 0.0f;

    // ---- async chunk loader: 128 rows x 128B for A and B ----
    auto load_chunk = [&](int c, int buf) {
        const int k0 = c * KC;
        const uint32_t a_base = smb + buf * 2 * BUF_BYTES;
        const uint32_t b_base = a_base + BUF_BYTES;
        #pragma unroll
        for (int q = 0; q < 4; q++) {
            int i = tid + q * 256;           // 0..1023
            int row = i >> 3;                // 0..127
            int seg = i & 7;                 // 0..7 (16B segments)
            uint32_t sw = SWZ128((uint32_t)(row * ROWB + seg * 16));
            const char* ga = xa + (size_t)row * (DD * 2) + (size_t)(k0 + seg * 8) * 2;
            const char* gb = xb + (size_t)row * (DD * 2) + (size_t)(k0 + seg * 8) * 2;
            CP_ASYNC16(a_base + sw, ga);
            CP_ASYNC16(b_base + sw, gb);
        }
    };

    load_chunk(0, 0);
    CP_COMMIT();

    for (int c = 0; c < NCHUNK; c++) {
        const int buf = c & 1;
        if (c + 1 < NCHUNK) {
            load_chunk(c + 1, buf ^ 1);
            CP_COMMIT();
            CP_WAIT1();
        } else {
            CP_WAIT0();
        }
        __syncthreads();

        const uint32_t a_base = smb + buf * 2 * BUF_BYTES;
        const uint32_t b_base = a_base + BUF_BYTES;

        #pragma unroll
        for (int ks = 0; ks < KC / 16; ks++) {
            // A fragments: 2 m-tiles of 16x16
            uint32_t afr[2][4];
            #pragma unroll
            for (int mi = 0; mi < 2; mi++) {
                int row = m0 + mi * 16 + (lane & 15);
                int kch = ks * 2 + (lane >> 4);
                uint32_t addr = a_base + SWZ128((uint32_t)(row * ROWB + kch * 16));
                LDMATRIX_X4(afr[mi][0], afr[mi][1], afr[mi][2], afr[mi][3], addr);
            }
            // B fragments: 4 n-tiles of 16x16 (each = two n8 groups)
            uint32_t bfr[4][4];
            #pragma unroll
            for (int nt = 0; nt < 4; nt++) {
                int row = n0 + nt * 16 + (lane & 7) + ((lane & 16) ? 8 : 0);
                int kch = ks * 2 + ((lane >> 3) & 1);
                uint32_t addr = b_base + SWZ128((uint32_t)(row * ROWB + kch * 16));
                LDMATRIX_X4(bfr[nt][0], bfr[nt][1], bfr[nt][2], bfr[nt][3], addr);
            }
            #pragma unroll
            for (int mi = 0; mi < 2; mi++)
                #pragma unroll
                for (int nt = 0; nt < 4; nt++) {
                    MMA_BF16(acc[mi][nt * 2][0], acc[mi][nt * 2][1],
                             acc[mi][nt * 2][2], acc[mi][nt * 2][3],
                             afr[mi][0], afr[mi][1], afr[mi][2], afr[mi][3],
                             bfr[nt][0], bfr[nt][1]);
                    MMA_BF16(acc[mi][nt * 2 + 1][0], acc[mi][nt * 2 + 1][1],
                             acc[mi][nt * 2 + 1][2], acc[mi][nt * 2 + 1][3],
                             afr[mi][0], afr[mi][1], afr[mi][2], afr[mi][3],
                             bfr[nt][2], bfr[nt][3]);
                }
        }
        __syncthreads();
    }

    // ---- epilogue: row max from accumulators ----
    // acc element mapping (m16n8): regs {0,1}: row = lane>>2, cols = (lane&3)*2 + {0,1}
    //                              regs {2,3}: row += 8, same cols
    #pragma unroll
    for (int mi = 0; mi < 2; mi++) {
        int row_lo = m0 + mi * 16 + (lane >> 2);   // local t row
        int row_hi = row_lo + 8;
        float mx0 = -3.0f, mx1 = -3.0f;
        #pragma unroll
        for (int nj = 0; nj < 8; nj++) {
            int col = n0 + nj * 8 + (lane & 3) * 2;   // local s col
            if (!diag || col     < row_lo) mx0 = fmaxf(mx0, acc[mi][nj][0]);
            if (!diag || col + 1 < row_lo) mx0 = fmaxf(mx0, acc[mi][nj][1]);
            if (!diag || col     < row_hi) mx1 = fmaxf(mx1, acc[mi][nj][2]);
            if (!diag || col + 1 < row_hi) mx1 = fmaxf(mx1, acc[mi][nj][3]);
        }
        // reduce across the 4 lanes of the row quad
        mx0 = fmaxf(mx0, __shfl_xor_sync(0xffffffffu, mx0, 1));
        mx0 = fmaxf(mx0, __shfl_xor_sync(0xffffffffu, mx0, 2));
        mx1 = fmaxf(mx1, __shfl_xor_sync(0xffffffffu, mx1, 1));
        mx1 = fmaxf(mx1, __shfl_xor_sync(0xffffffffu, mx1, 2));
        if ((lane & 3) == 0) {
            if (mx0 > -2.5f) atomicMax(&g_m[(size_t)b * TT + t0 + row_lo], ford(mx0));
            if (mx1 > -2.5f) atomicMax(&g_m[(size_t)b * TT + t0 + row_hi], ford(mx1));
        }
    }
}

// ============================================================
// Kernel C: gate + tanh-GELU epilogue, float4 vectorized.
// ============================================================
__global__ void gate_gelu_kernel(const float* __restrict__ x,
                                 const float* __restrict__ log_alpha,
                                 float* __restrict__ out) {
    size_t idx = (size_t)blockIdx.x * blockDim.x + threadIdx.x;
    size_t total4 = (size_t)BB * TT * DD / 4;
    if (idx >= total4) return;

    float la = *log_alpha;
    float alpha = (la > 20.0f) ? la : log1pf(expf(la));

    size_t row = idx / (DD / 4);
    float m = funord(g_m[row]);
    m = fmaxf(m, -1.0f);
    float gate = 1.0f + alpha * 0.5f * (1.0f - m);

    float4 v = reinterpret_cast<const float4*>(x)[idx];
    const float c = 0.7978845608028654f;
    float r[4] = {v.x, v.y, v.z, v.w};
    #pragma unroll
    for (int i = 0; i < 4; i++) {
        float xv = r[i] * gate;
        float t = tanhf(c * (xv + 0.044715f * xv * xv * xv));
        r[i] = 0.5f * xv * (1.0f + t);
    }
    float4 o = {r[0], r[1], r[2], r[3]};
    reinterpret_cast<float4*>(out)[idx] = o;
}

extern "C" void kernel_launch(void* const* d_in, const int* in_sizes, int n_in,
                              void* d_out, int out_size) {
    const float* x  = (const float*)d_in[0];
    const float* la = (const float*)d_in[1];
    float* out = (float*)d_out;

    normalize_kernel<<<BB * TT, 128>>>(x);

    cudaFuncSetAttribute(simmax_mma_kernel,
                         cudaFuncAttributeMaxDynamicSharedMemorySize, SM_TOTAL);
    int ntiles = (TT / TM) * (TT / TM + 1) / 2;   // 528
    dim3 grid(ntiles, BB);
    simmax_mma_kernel<<<grid, 256, SM_TOTAL>>>();

    size_t total4 = (size_t)BB * TT * DD / 4;
    int threads = 256;
    int blocks = (int)((total4 + threads - 1) / threads);
    gate_gelu_kernel<<<blocks, threads>>>(x, la, out);
}

// round 4
// speedup vs baseline: 11.0599x; 1.0648x over previous
#include <cuda_runtime.h>
#include <cuda_bf16.h>
#include <cstdint>

// Problem constants
#define BB 4
#define TT 4096
#define DD 512

// ---------------- scratch (__device__ globals; no allocs allowed) ----------
__device__ __nv_bfloat16 g_xnb[(size_t)BB * TT * DD];  // normalized x, bf16
__device__ unsigned      g_m[(size_t)BB * TT];         // per-row max sim (order-encoded)

// ---- order-preserving float <-> uint for atomicMax ----
__device__ __forceinline__ unsigned ford(float f) {
    unsigned u = __float_as_uint(f);
    return (u & 0x80000000u) ? ~u : (u | 0x80000000u);
}
__device__ __forceinline__ float funord(unsigned u) {
    return __uint_as_float((u & 0x80000000u) ? (u ^ 0x80000000u) : ~u);
}

__device__ __forceinline__ uint32_t smem_u32(const void* p) {
    uint32_t a;
    asm("{ .reg .u64 t; cvta.to.shared.u64 t, %1; cvt.u32.u64 %0, t; }" : "=r"(a) : "l"(p));
    return a;
}

#define SWZ128(off) ((off) ^ (((off) >> 3) & 0x70))

#define CP_ASYNC16(sm, gm) \
    asm volatile("cp.async.cg.shared.global [%0], [%1], 16;" :: "r"(sm), "l"(gm) : "memory")
#define CP_COMMIT() asm volatile("cp.async.commit_group;" ::: "memory")
#define CP_WAIT1()  asm volatile("cp.async.wait_group 1;" ::: "memory")
#define CP_WAIT0()  asm volatile("cp.async.wait_group 0;" ::: "memory")

#define LDMATRIX_X4(r0, r1, r2, r3, addr) \
    asm volatile("ldmatrix.sync.aligned.m8n8.x4.shared.b16 {%0,%1,%2,%3}, [%4];" \
                 : "=r"(r0), "=r"(r1), "=r"(r2), "=r"(r3) : "r"(addr))

#define MMA_BF16(c0, c1, c2, c3, a0, a1, a2, a3, b0, b1) \
    asm volatile("mma.sync.aligned.m16n8k16.row.col.f32.bf16.bf16.f32 " \
                 "{%0,%1,%2,%3}, {%4,%5,%6,%7}, {%8,%9}, {%0,%1,%2,%3};" \
                 : "+f"(c0), "+f"(c1), "+f"(c2), "+f"(c3) \
                 : "r"(a0), "r"(a1), "r"(a2), "r"(a3), "r"(b0), "r"(b1))

// ============================================================
// Kernel A: per-row L2 normalize -> bf16; one warp per row.
// block = 256 threads = 8 rows; grid = B*T/8 = 2048.
// ============================================================
__global__ __launch_bounds__(256) void normalize_kernel(const float* __restrict__ x) {
    const int warp = threadIdx.x >> 5;
    const int lane = threadIdx.x & 31;
    const int row = blockIdx.x * 8 + warp;

    const float4* xin = reinterpret_cast<const float4*>(x + (size_t)row * DD);
    float4 v[4];
    float ss = 0.0f;
    #pragma unroll
    for (int i = 0; i < 4; i++) {
        v[i] = xin[lane + i * 32];
        ss += v[i].x * v[i].x + v[i].y * v[i].y + v[i].z * v[i].z + v[i].w * v[i].w;
    }
    #pragma unroll
    for (int off = 16; off > 0; off >>= 1)
        ss += __shfl_xor_sync(0xffffffffu, ss, off);
    float scale = 1.0f / fmaxf(sqrtf(ss), 1e-12f);

    uint2* xo = reinterpret_cast<uint2*>(g_xnb + (size_t)row * DD);
    #pragma unroll
    for (int i = 0; i < 4; i++) {
        __nv_bfloat162 p0 = __floats2bfloat162_rn(v[i].x * scale, v[i].y * scale);
        __nv_bfloat162 p1 = __floats2bfloat162_rn(v[i].z * scale, v[i].w * scale);
        uint2 o;
        o.x = *reinterpret_cast<unsigned*>(&p0);
        o.y = *reinterpret_cast<unsigned*>(&p1);
        xo[lane + i * 32] = o;
    }
    if (lane == 0) g_m[row] = ford(-2.0f);
}

// ============================================================
// Kernel B: mma.sync bf16 sim-max. CTA tile 128x128, 8 warps
// (4m x 2n), warp tile 32x64, K in 8 chunks of 64, cp.async
// double buffer, SW128-swizzled smem, row-max from registers.
// 2 CTAs/SM via launch_bounds. grid = (528 pairs, B)
// ============================================================
#define TM 128
#define KC 64
#define NCHUNK (DD / KC)     // 8
#define ROWB 128             // bytes per smem row (64 bf16)
#define BUF_BYTES (TM * ROWB)   // 16 KB per tile buffer
#define SM_TOTAL (4 * BUF_BYTES)

__global__ __launch_bounds__(256, 2) void simmax_mma_kernel() {
    extern __shared__ char smem[];
    const uint32_t smb = smem_u32(smem);
    const int tid = threadIdx.x;
    const int wid = tid >> 5;
    const int lane = tid & 31;

    // decode lower-triangular pair index -> (t_tile, s_tile)
    int p = blockIdx.x;
    int t_tile = (int)((sqrtf(8.0f * (float)p + 1.0f) - 1.0f) * 0.5f);
    while ((t_tile + 1) * (t_tile + 2) / 2 <= p) ++t_tile;
    while (t_tile * (t_tile + 1) / 2 > p) --t_tile;
    int s_tile = p - t_tile * (t_tile + 1) / 2;
    const int b = blockIdx.y;
    const int t0 = t_tile * TM;
    const int s0 = s_tile * TM;
    const bool diag = (s_tile == t_tile);

    const char* xa = reinterpret_cast<const char*>(g_xnb + ((size_t)b * TT + t0) * DD);
    const char* xb = reinterpret_cast<const char*>(g_xnb + ((size_t)b * TT + s0) * DD);

    const int warp_m = wid & 3;        // 0..3 -> 32 rows each
    const int warp_n = wid >> 2;       // 0..1 -> 64 cols each
    const int m0 = warp_m * 32;
    const int n0 = warp_n * 64;

    float acc[2][8][4];
    #pragma unroll
    for (int mi = 0; mi < 2; mi++)
        #pragma unroll
        for (int nj = 0; nj < 8; nj++)
            #pragma unroll
            for (int r = 0; r < 4; r++) acc[mi][nj][r] = 0.0f;

    // precomputed per-thread ldmatrix address components
    const int a_row_base = m0 + (lane & 15);
    const int a_k_half   = (lane >> 4);               // 0/1
    const int b_row_base = n0 + (lane & 7) + ((lane & 16) ? 8 : 0);
    const int b_k_half   = ((lane >> 3) & 1);

    // ---- async chunk loader: 128 rows x 128B for A and B ----
    auto load_chunk = [&](int c, int buf) {
        const int k0 = c * KC;
        const uint32_t a_base = smb + buf * 2 * BUF_BYTES;
        const uint32_t b_base = a_base + BUF_BYTES;
        #pragma unroll
        for (int q = 0; q < 4; q++) {
            int i = tid + q * 256;           // 0..1023
            int row = i >> 3;                // 0..127
            int seg = i & 7;                 // 0..7 (16B segments)
            uint32_t sw = SWZ128((uint32_t)(row * ROWB + seg * 16));
            const char* ga = xa + (size_t)row * (DD * 2) + (size_t)(k0 + seg * 8) * 2;
            const char* gb = xb + (size_t)row * (DD * 2) + (size_t)(k0 + seg * 8) * 2;
            CP_ASYNC16(a_base + sw, ga);
            CP_ASYNC16(b_base + sw, gb);
        }
    };

    load_chunk(0, 0);
    CP_COMMIT();

    for (int c = 0; c < NCHUNK; c++) {
        const int buf = c & 1;
        if (c + 1 < NCHUNK) {
            load_chunk(c + 1, buf ^ 1);
            CP_COMMIT();
            CP_WAIT1();
        } else {
            CP_WAIT0();
        }
        __syncthreads();

        const uint32_t a_base = smb + buf * 2 * BUF_BYTES;
        const uint32_t b_base = a_base + BUF_BYTES;

        #pragma unroll
        for (int ks = 0; ks < KC / 16; ks++) {
            uint32_t afr[2][4];
            #pragma unroll
            for (int mi = 0; mi < 2; mi++) {
                int row = a_row_base + mi * 16;
                int kch = ks * 2 + a_k_half;
                uint32_t addr = a_base + SWZ128((uint32_t)(row * ROWB + kch * 16));
                LDMATRIX_X4(afr[mi][0], afr[mi][1], afr[mi][2], afr[mi][3], addr);
            }
            uint32_t bfr[4][4];
            #pragma unroll
            for (int nt = 0; nt < 4; nt++) {
                int row = b_row_base + nt * 16;
                int kch = ks * 2 + b_k_half;
                uint32_t addr = b_base + SWZ128((uint32_t)(row * ROWB + kch * 16));
                LDMATRIX_X4(bfr[nt][0], bfr[nt][1], bfr[nt][2], bfr[nt][3], addr);
            }
            #pragma unroll
            for (int mi = 0; mi < 2; mi++)
                #pragma unroll
                for (int nt = 0; nt < 4; nt++) {
                    MMA_BF16(acc[mi][nt * 2][0], acc[mi][nt * 2][1],
                             acc[mi][nt * 2][2], acc[mi][nt * 2][3],
                             afr[mi][0], afr[mi][1], afr[mi][2], afr[mi][3],
                             bfr[nt][0], bfr[nt][1]);
                    MMA_BF16(acc[mi][nt * 2 + 1][0], acc[mi][nt * 2 + 1][1],
                             acc[mi][nt * 2 + 1][2], acc[mi][nt * 2 + 1][3],
                             afr[mi][0], afr[mi][1], afr[mi][2], afr[mi][3],
                             bfr[nt][2], bfr[nt][3]);
                }
        }
        __syncthreads();
    }

    // ---- epilogue: row max from accumulators ----
    #pragma unroll
    for (int mi = 0; mi < 2; mi++) {
        int row_lo = m0 + mi * 16 + (lane >> 2);
        int row_hi = row_lo + 8;
        float mx0 = -3.0f, mx1 = -3.0f;
        #pragma unroll
        for (int nj = 0; nj < 8; nj++) {
            int col = n0 + nj * 8 + (lane & 3) * 2;
            if (!diag || col     < row_lo) mx0 = fmaxf(mx0, acc[mi][nj][0]);
            if (!diag || col + 1 < row_lo) mx0 = fmaxf(mx0, acc[mi][nj][1]);
            if (!diag || col     < row_hi) mx1 = fmaxf(mx1, acc[mi][nj][2]);
            if (!diag || col + 1 < row_hi) mx1 = fmaxf(mx1, acc[mi][nj][3]);
        }
        mx0 = fmaxf(mx0, __shfl_xor_sync(0xffffffffu, mx0, 1));
        mx0 = fmaxf(mx0, __shfl_xor_sync(0xffffffffu, mx0, 2));
        mx1 = fmaxf(mx1, __shfl_xor_sync(0xffffffffu, mx1, 1));
        mx1 = fmaxf(mx1, __shfl_xor_sync(0xffffffffu, mx1, 2));
        if ((lane & 3) == 0) {
            if (mx0 > -2.5f) atomicMax(&g_m[(size_t)b * TT + t0 + row_lo], ford(mx0));
            if (mx1 > -2.5f) atomicMax(&g_m[(size_t)b * TT + t0 + row_hi], ford(mx1));
        }
    }
}

// ============================================================
// Kernel C: gate + tanh-GELU epilogue, float4 vectorized.
// ============================================================
__global__ void gate_gelu_kernel(const float* __restrict__ x,
                                 const float* __restrict__ log_alpha,
                                 float* __restrict__ out) {
    size_t idx = (size_t)blockIdx.x * blockDim.x + threadIdx.x;
    size_t total4 = (size_t)BB * TT * DD / 4;
    if (idx >= total4) return;

    float la = *log_alpha;
    float alpha = (la > 20.0f) ? la : log1pf(expf(la));

    size_t row = idx / (DD / 4);
    float m = funord(g_m[row]);
    m = fmaxf(m, -1.0f);
    float gate = 1.0f + alpha * 0.5f * (1.0f - m);

    float4 v = reinterpret_cast<const float4*>(x)[idx];
    const float c = 0.7978845608028654f;
    float r[4] = {v.x, v.y, v.z, v.w};
    #pragma unroll
    for (int i = 0; i < 4; i++) {
        float xv = r[i] * gate;
        float t = tanhf(c * (xv + 0.044715f * xv * xv * xv));
        r[i] = 0.5f * xv * (1.0f + t);
    }
    float4 o = {r[0], r[1], r[2], r[3]};
    reinterpret_cast<float4*>(out)[idx] = o;
}

extern "C" void kernel_launch(void* const* d_in, const int* in_sizes, int n_in,
                              void* d_out, int out_size) {
    const float* x  = (const float*)d_in[0];
    const float* la = (const float*)d_in[1];
    float* out = (float*)d_out;

    normalize_kernel<<<BB * TT / 8, 256>>>(x);

    cudaFuncSetAttribute(simmax_mma_kernel,
                         cudaFuncAttributeMaxDynamicSharedMemorySize, SM_TOTAL);
    int ntiles = (TT / TM) * (TT / TM + 1) / 2;   // 528
    dim3 grid(ntiles, BB);
    simmax_mma_kernel<<<grid, 256, SM_TOTAL>>>();

    size_t total4 = (size_t)BB * TT * DD / 4;
    int threads = 256;
    int blocks = (int)((total4 + threads - 1) / threads);
    gate_gelu_kernel<<<blocks, threads>>>(x, la, out);
}

// round 5
// speedup vs baseline: 11.7975x; 1.0667x over previous
#include <cuda_runtime.h>
#include <cuda_bf16.h>
#include <cstdint>

// Problem constants
#define BB 4
#define TT 4096
#define DD 512

// ---------------- scratch (__device__ globals; no allocs allowed) ----------
__device__ __nv_bfloat16 g_xnb[(size_t)BB * TT * DD];  // normalized x, bf16
__device__ unsigned      g_m[(size_t)BB * TT];         // per-row max sim (order-encoded)

// ---- order-preserving float <-> uint for atomicMax ----
__device__ __forceinline__ unsigned ford(float f) {
    unsigned u = __float_as_uint(f);
    return (u & 0x80000000u) ? ~u : (u | 0x80000000u);
}
__device__ __forceinline__ float funord(unsigned u) {
    return __uint_as_float((u & 0x80000000u) ? (u ^ 0x80000000u) : ~u);
}

__device__ __forceinline__ uint32_t smem_u32(const void* p) {
    uint32_t a;
    asm("{ .reg .u64 t; cvta.to.shared.u64 t, %1; cvt.u32.u64 %0, t; }" : "=r"(a) : "l"(p));
    return a;
}

#define SWZ128(off) ((off) ^ (((off) >> 3) & 0x70))

#define CP_ASYNC16(sm, gm) \
    asm volatile("cp.async.cg.shared.global [%0], [%1], 16;" :: "r"(sm), "l"(gm) : "memory")
#define CP_COMMIT() asm volatile("cp.async.commit_group;" ::: "memory")
#define CP_WAIT1()  asm volatile("cp.async.wait_group 1;" ::: "memory")
#define CP_WAIT0()  asm volatile("cp.async.wait_group 0;" ::: "memory")

#define LDMATRIX_X4(r0, r1, r2, r3, addr) \
    asm volatile("ldmatrix.sync.aligned.m8n8.x4.shared.b16 {%0,%1,%2,%3}, [%4];" \
                 : "=r"(r0), "=r"(r1), "=r"(r2), "=r"(r3) : "r"(addr))

#define MMA_BF16(c0, c1, c2, c3, a0, a1, a2, a3, b0, b1) \
    asm volatile("mma.sync.aligned.m16n8k16.row.col.f32.bf16.bf16.f32 " \
                 "{%0,%1,%2,%3}, {%4,%5,%6,%7}, {%8,%9}, {%0,%1,%2,%3};" \
                 : "+f"(c0), "+f"(c1), "+f"(c2), "+f"(c3) \
                 : "r"(a0), "r"(a1), "r"(a2), "r"(a3), "r"(b0), "r"(b1))

// ============================================================
// Kernel A: per-row L2 normalize -> bf16; one warp per row.
// ============================================================
__global__ __launch_bounds__(256) void normalize_kernel(const float* __restrict__ x) {
    const int warp = threadIdx.x >> 5;
    const int lane = threadIdx.x & 31;
    const int row = blockIdx.x * 8 + warp;

    const float4* xin = reinterpret_cast<const float4*>(x + (size_t)row * DD);
    float4 v[4];
    float ss = 0.0f;
    #pragma unroll
    for (int i = 0; i < 4; i++) {
        v[i] = xin[lane + i * 32];
        ss += v[i].x * v[i].x + v[i].y * v[i].y + v[i].z * v[i].z + v[i].w * v[i].w;
    }
    #pragma unroll
    for (int off = 16; off > 0; off >>= 1)
        ss += __shfl_xor_sync(0xffffffffu, ss, off);
    float scale = 1.0f / fmaxf(sqrtf(ss), 1e-12f);

    uint2* xo = reinterpret_cast<uint2*>(g_xnb + (size_t)row * DD);
    #pragma unroll
    for (int i = 0; i < 4; i++) {
        __nv_bfloat162 p0 = __floats2bfloat162_rn(v[i].x * scale, v[i].y * scale);
        __nv_bfloat162 p1 = __floats2bfloat162_rn(v[i].z * scale, v[i].w * scale);
        uint2 o;
        o.x = *reinterpret_cast<unsigned*>(&p0);
        o.y = *reinterpret_cast<unsigned*>(&p1);
        xo[lane + i * 32] = o;
    }
    if (lane == 0) g_m[row] = ford(-2.0f);
}

// ============================================================
// Kernel B: mma.sync bf16 sim-max. CTA tile 128x128, 8 warps
// (4m x 2n), warp tile 32x64. K in 8 chunks of 64, 3-stage
// cp.async pipeline, 1 sync per chunk, folded swizzle addrs.
// grid = (528 lower-tri pairs, B), 2 CTAs/SM.
// ============================================================
#define TM 128
#define KC 64
#define NCHUNK (DD / KC)        // 8
#define ROWB 128                // bytes per smem row (64 bf16)
#define BUF_BYTES (TM * ROWB)   // 16 KB per tile buffer
#define NSTAGE 3
#define SM_TOTAL (NSTAGE * 2 * BUF_BYTES)   // 96 KB

__global__ __launch_bounds__(256, 2) void simmax_mma_kernel() {
    extern __shared__ char smem[];
    const uint32_t smb = smem_u32(smem);
    const int tid = threadIdx.x;
    const int wid = tid >> 5;
    const int lane = tid & 31;

    // decode lower-triangular pair index -> (t_tile, s_tile)
    int p = blockIdx.x;
    int t_tile = (int)((sqrtf(8.0f * (float)p + 1.0f) - 1.0f) * 0.5f);
    while ((t_tile + 1) * (t_tile + 2) / 2 <= p) ++t_tile;
    while (t_tile * (t_tile + 1) / 2 > p) --t_tile;
    int s_tile = p - t_tile * (t_tile + 1) / 2;
    const int b = blockIdx.y;
    const int t0 = t_tile * TM;
    const int s0 = s_tile * TM;
    const bool diag = (s_tile == t_tile);

    const char* xa = reinterpret_cast<const char*>(g_xnb + ((size_t)b * TT + t0) * DD);
    const char* xb = reinterpret_cast<const char*>(g_xnb + ((size_t)b * TT + s0) * DD);

    const int warp_m = wid & 3;
    const int warp_n = wid >> 2;
    const int m0 = warp_m * 32;
    const int n0 = warp_n * 64;

    float acc[2][8][4];
    #pragma unroll
    for (int mi = 0; mi < 2; mi++)
        #pragma unroll
        for (int nj = 0; nj < 8; nj++)
            #pragma unroll
            for (int r = 0; r < 4; r++) acc[mi][nj][r] = 0.0f;

    // ---- folded swizzle base addresses (within a tile buffer) ----
    // off = row*128 + (ks*32 | half*16); mask = ((row*128)>>3)&0x70 depends
    // only on row -> swz(off) = (row*128 | (half16 ^ mask)) ^ ks32
    uint32_t a_sw[2], b_sw[4];
    {
        const int a_half16 = (lane >> 4) * 16;
        #pragma unroll
        for (int mi = 0; mi < 2; mi++) {
            uint32_t rb = (uint32_t)((m0 + mi * 16 + (lane & 15)) * ROWB);
            uint32_t mask = (rb >> 3) & 0x70;
            a_sw[mi] = rb | (a_half16 ^ mask);
        }
        const int b_half16 = ((lane >> 3) & 1) * 16;
        #pragma unroll
        for (int nt = 0; nt < 4; nt++) {
            uint32_t rb = (uint32_t)((n0 + nt * 16 + (lane & 7) + ((lane & 16) ? 8 : 0)) * ROWB);
            uint32_t mask = (rb >> 3) & 0x70;
            b_sw[nt] = rb | (b_half16 ^ mask);
        }
    }

    // loader-side precompute: thread's (row, seg) and swizzled offset
    const int ld_row = tid >> 3;            // base row (advance by 32 per q)
    const int ld_seg = tid & 7;
    uint32_t ld_sw[4];
    const char* ld_ga[4];
    const char* ld_gb[4];
    #pragma unroll
    for (int q = 0; q < 4; q++) {
        int row = ld_row + q * 32;
        ld_sw[q] = SWZ128((uint32_t)(row * ROWB + ld_seg * 16));
        ld_ga[q] = xa + (size_t)row * (DD * 2) + (size_t)(ld_seg * 8) * 2;
        ld_gb[q] = xb + (size_t)row * (DD * 2) + (size_t)(ld_seg * 8) * 2;
    }

    auto load_chunk = [&](int c) {
        const int buf = c % NSTAGE;
        const size_t koff = (size_t)(c * KC) * 2;
        const uint32_t a_base = smb + buf * 2 * BUF_BYTES;
        const uint32_t b_base = a_base + BUF_BYTES;
        #pragma unroll
        for (int q = 0; q < 4; q++) {
            CP_ASYNC16(a_base + ld_sw[q], ld_ga[q] + koff);
            CP_ASYNC16(b_base + ld_sw[q], ld_gb[q] + koff);
        }
        CP_COMMIT();
    };

    load_chunk(0);
    load_chunk(1);

    for (int c = 0; c < NCHUNK; c++) {
        const int buf = c % NSTAGE;
        if (c == NCHUNK - 1) { CP_WAIT0(); } else { CP_WAIT1(); }
        __syncthreads();
        if (c + 2 < NCHUNK) load_chunk(c + 2);

        const uint32_t a_base = smb + buf * 2 * BUF_BYTES;
        const uint32_t b_base = a_base + BUF_BYTES;

        #pragma unroll
        for (int ks = 0; ks < KC / 16; ks++) {
            const uint32_t ks32 = (uint32_t)(ks * 32);
            uint32_t afr[2][4];
            #pragma unroll
            for (int mi = 0; mi < 2; mi++)
                LDMATRIX_X4(afr[mi][0], afr[mi][1], afr[mi][2], afr[mi][3],
                            a_base + (a_sw[mi] ^ ks32));
            uint32_t bfr[4][4];
            #pragma unroll
            for (int nt = 0; nt < 4; nt++)
                LDMATRIX_X4(bfr[nt][0], bfr[nt][1], bfr[nt][2], bfr[nt][3],
                            b_base + (b_sw[nt] ^ ks32));
            #pragma unroll
            for (int mi = 0; mi < 2; mi++)
                #pragma unroll
                for (int nt = 0; nt < 4; nt++) {
                    MMA_BF16(acc[mi][nt * 2][0], acc[mi][nt * 2][1],
                             acc[mi][nt * 2][2], acc[mi][nt * 2][3],
                             afr[mi][0], afr[mi][1], afr[mi][2], afr[mi][3],
                             bfr[nt][0], bfr[nt][1]);
                    MMA_BF16(acc[mi][nt * 2 + 1][0], acc[mi][nt * 2 + 1][1],
                             acc[mi][nt * 2 + 1][2], acc[mi][nt * 2 + 1][3],
                             afr[mi][0], afr[mi][1], afr[mi][2], afr[mi][3],
                             bfr[nt][2], bfr[nt][3]);
                }
        }
    }

    // ---- epilogue: row max from accumulators ----
    #pragma unroll
    for (int mi = 0; mi < 2; mi++) {
        int row_lo = m0 + mi * 16 + (lane >> 2);
        int row_hi = row_lo + 8;
        float mx0 = -3.0f, mx1 = -3.0f;
        #pragma unroll
        for (int nj = 0; nj < 8; nj++) {
            int col = n0 + nj * 8 + (lane & 3) * 2;
            if (!diag || col     < row_lo) mx0 = fmaxf(mx0, acc[mi][nj][0]);
            if (!diag || col + 1 < row_lo) mx0 = fmaxf(mx0, acc[mi][nj][1]);
            if (!diag || col     < row_hi) mx1 = fmaxf(mx1, acc[mi][nj][2]);
            if (!diag || col + 1 < row_hi) mx1 = fmaxf(mx1, acc[mi][nj][3]);
        }
        mx0 = fmaxf(mx0, __shfl_xor_sync(0xffffffffu, mx0, 1));
        mx0 = fmaxf(mx0, __shfl_xor_sync(0xffffffffu, mx0, 2));
        mx1 = fmaxf(mx1, __shfl_xor_sync(0xffffffffu, mx1, 1));
        mx1 = fmaxf(mx1, __shfl_xor_sync(0xffffffffu, mx1, 2));
        if ((lane & 3) == 0) {
            if (mx0 > -2.5f) atomicMax(&g_m[(size_t)b * TT + t0 + row_lo], ford(mx0));
            if (mx1 > -2.5f) atomicMax(&g_m[(size_t)b * TT + t0 + row_hi], ford(mx1));
        }
    }
}

// ============================================================
// Kernel C: gate + tanh-GELU epilogue, float4 vectorized.
// ============================================================
__global__ void gate_gelu_kernel(const float* __restrict__ x,
                                 const float* __restrict__ log_alpha,
                                 float* __restrict__ out) {
    size_t idx = (size_t)blockIdx.x * blockDim.x + threadIdx.x;
    size_t total4 = (size_t)BB * TT * DD / 4;
    if (idx >= total4) return;

    float la = *log_alpha;
    float alpha = (la > 20.0f) ? la : log1pf(expf(la));

    size_t row = idx / (DD / 4);
    float m = funord(g_m[row]);
    m = fmaxf(m, -1.0f);
    float gate = 1.0f + alpha * 0.5f * (1.0f - m);

    float4 v = reinterpret_cast<const float4*>(x)[idx];
    const float c = 0.7978845608028654f;
    float r[4] = {v.x, v.y, v.z, v.w};
    #pragma unroll
    for (int i = 0; i < 4; i++) {
        float xv = r[i] * gate;
        float t = tanhf(c * (xv + 0.044715f * xv * xv * xv));
        r[i] = 0.5f * xv * (1.0f + t);
    }
    float4 o = {r[0], r[1], r[2], r[3]};
    reinterpret_cast<float4*>(out)[idx] = o;
}

extern "C" void kernel_launch(void* const* d_in, const int* in_sizes, int n_in,
                              void* d_out, int out_size) {
    const float* x  = (const float*)d_in[0];
    const float* la = (const float*)d_in[1];
    float* out = (float*)d_out;

    normalize_kernel<<<BB * TT / 8, 256>>>(x);

    cudaFuncSetAttribute(simmax_mma_kernel,
                         cudaFuncAttributeMaxDynamicSharedMemorySize, SM_TOTAL);
    int ntiles = (TT / TM) * (TT / TM + 1) / 2;   // 528
    dim3 grid(ntiles, BB);
    simmax_mma_kernel<<<grid, 256, SM_TOTAL>>>();

    size_t total4 = (size_t)BB * TT * DD / 4;
    int threads = 256;
    int blocks = (int)((total4 + threads - 1) / threads);
    gate_gelu_kernel<<<blocks, threads>>>(x, la, out);
}